// round 16
// baseline (speedup 1.0000x reference)
#include <cuda_runtime.h>
#include <cuda_bf16.h>
#include <cstdint>

#define BB   2
#define SS   2048
#define DD   1024
#define HH   16
#define HDIM 64
#define MM   (BB*SS)

// ---------------- scratch (__device__ globals; allocation-free rule) -------
__device__ __nv_bfloat16 g_Qh[BB*HH*SS*HDIM], g_Ql[BB*HH*SS*HDIM];  // [bh][s][c], scaled log2e/32
__device__ __nv_bfloat16 g_Kh[BB*HH*SS*HDIM], g_Kl[BB*HH*SS*HDIM];  // [bh][s][c]
__device__ __nv_bfloat16 g_Vth[BB*HH*SS*HDIM], g_Vtl[BB*HH*SS*HDIM];// [bh][c][s] transposed
__device__ __nv_bfloat16 g_Xh[MM*DD],  g_Xl[MM*DD];                 // x split hi/lo
__device__ __nv_bfloat16 g_Wh[4*DD*DD], g_Wl[4*DD*DD];              // W^T (permuted) hi/lo
__device__ __nv_bfloat16 g_Ah[MM*DD],  g_Al[MM*DD];                 // attn out [b][s][h*64+c]

// ---------------- helpers ---------------------------------------------------
__device__ __forceinline__ uint32_t smem_u32(const void* p) {
    uint32_t a;
    asm("{ .reg .u64 t; cvta.to.shared.u64 t, %1; cvt.u32.u64 %0, t; }" : "=r"(a) : "l"(p));
    return a;
}
__device__ __forceinline__ void cp16(uint32_t dst, const void* src) {
    asm volatile("cp.async.ca.shared.global [%0], [%1], 16;" :: "r"(dst), "l"(src));
}
#define CP_COMMIT() asm volatile("cp.async.commit_group;" ::: "memory")
#define CP_WAIT(n)  asm volatile("cp.async.wait_group %0;" :: "n"(n) : "memory")

#define LDSM_X4(r, a)                                                        \
    asm volatile("ldmatrix.sync.aligned.m8n8.x4.shared.b16 {%0,%1,%2,%3}, [%4];" \
        : "=r"((r)[0]), "=r"((r)[1]), "=r"((r)[2]), "=r"((r)[3]) : "r"(a))

#define MMA16816(d, a, b)                                                    \
    asm volatile("mma.sync.aligned.m16n8k16.row.col.f32.bf16.bf16.f32 "      \
        "{%0,%1,%2,%3}, {%4,%5,%6,%7}, {%8,%9}, {%0,%1,%2,%3};"              \
        : "+f"((d)[0]), "+f"((d)[1]), "+f"((d)[2]), "+f"((d)[3])             \
        : "r"((a)[0]), "r"((a)[1]), "r"((a)[2]), "r"((a)[3]),                \
          "r"((b)[0]), "r"((b)[1]))

__device__ __forceinline__ uint32_t prmt(uint32_t a, uint32_t b, uint32_t sel) {
    uint32_t r;
    asm("prmt.b32 %0, %1, %2, %3;" : "=r"(r) : "r"(a), "r"(b), "r"(sel));
    return r;
}
__device__ __forceinline__ float ex2(float x) {
    float r;
    asm("ex2.approx.f32 %0, %1;" : "=f"(r) : "f"(x));
    return r;
}

// truncation-based hi/lo bf16 split of (v0,v1): hi packed return, lo out-param.
__device__ __forceinline__ uint32_t split_pack(float v0, float v1, uint32_t& lo) {
    uint32_t u0 = __float_as_uint(v0), u1 = __float_as_uint(v1);
    uint32_t hi = prmt(u0, u1, 0x7632);
    float h0 = __uint_as_float(u0 & 0xFFFF0000u);
    float h1 = __uint_as_float(u1 & 0xFFFF0000u);
    lo = prmt(__float_as_uint(v0 - h0), __float_as_uint(v1 - h1), 0x7632);
    return hi;
}

// ---------------- prep kernels ---------------------------------------------
__global__ __launch_bounds__(256)
void split_x(const float* __restrict__ x)
{
    int i = blockIdx.x * 256 + threadIdx.x;
    float v = x[i];
    __nv_bfloat16 h = __float2bfloat16(v);
    g_Xh[i] = h;
    g_Xl[i] = __float2bfloat16(v - __bfloat162float(h));
}

// z<3 (qw,kw,vw): W^T with head-permuted columns; z==3 (ow): W^T with permuted k.
__global__ void prep_w(const float* __restrict__ qw, const float* __restrict__ kw,
                       const float* __restrict__ vw, const float* __restrict__ ow)
{
    __shared__ float tile[32][33];
    int z = blockIdx.z;
    const float* W = (z == 0) ? qw : (z == 1) ? kw : (z == 2) ? vw : ow;
    int kbase = blockIdx.y * 32, jbase = blockIdx.x * 32;
    int tx = threadIdx.x, ty = threadIdx.y;
    tile[ty][tx] = W[(kbase + ty) * DD + jbase + tx];
    __syncthreads();
    int j = jbase + ty;
    int k = kbase + tx;
    float v = tile[tx][ty];                 // = W[k][j]
    __nv_bfloat16 h = __float2bfloat16(v);
    size_t o;
    if (z < 3) {
        int jp = (j & 15) * 64 + (j >> 4);
        o = (size_t)z * DD * DD + (size_t)jp * DD + k;
    } else {
        int kp = (k & 15) * 64 + (k >> 4);
        o = (size_t)3 * DD * DD + (size_t)j * DD + kp;
    }
    g_Wh[o] = h;
    g_Wl[o] = __float2bfloat16(v - __bfloat162float(h));
}

// ---------------- mma.sync GEMM mainloop (round-14 proven, unchanged) -------
#define GMAT    18432
#define STAGE_B (4 * GMAT)
#define GSMEM   (2 * STAGE_B)               // 147456
#define NITER   (DD / 64)                   // 16

__device__ __forceinline__ void load_stage(
    uint32_t sb, int s, int kt,
    const __nv_bfloat16* __restrict__ Ah, const __nv_bfloat16* __restrict__ Al,
    const __nv_bfloat16* __restrict__ Bh, const __nv_bfloat16* __restrict__ Bl,
    int rowbase, int colbase, int tid)
{
    uint32_t base = sb + s * STAGE_B;
#pragma unroll
    for (int t = 0; t < 16; t++) {
        int f = tid + t * 256;
        int mat = f >> 10;                  // 0:Ah 1:Al 2:Bh 3:Bl
        int w = f & 1023;
        int r = w >> 3, c = w & 7;          // row 0-127, 16B chunk 0-7
        int rb = (mat < 2) ? rowbase : colbase;
        const __nv_bfloat16* src = ((mat == 0) ? Ah : (mat == 1) ? Al :
                                    (mat == 2) ? Bh : Bl) +
                                   (size_t)(rb + r) * DD + kt + c * 8;
        cp16(base + mat * GMAT + r * 144 + c * 16, src);
    }
}

__device__ __forceinline__ void gemm_mainloop_mma(
    const __nv_bfloat16* __restrict__ Ah, const __nv_bfloat16* __restrict__ Al,
    const __nv_bfloat16* __restrict__ Bh, const __nv_bfloat16* __restrict__ Bl,
    int rowbase, int colbase, char* smem, float d[4][4][4])
{
    uint32_t sb = smem_u32(smem);
    int tid = threadIdx.x;
    int lane = tid & 31, warp = tid >> 5;
    int wm = warp >> 2, wn = warp & 3;

#pragma unroll
    for (int mt = 0; mt < 4; mt++)
#pragma unroll
        for (int nt = 0; nt < 4; nt++)
#pragma unroll
            for (int e = 0; e < 4; e++) d[mt][nt][e] = 0.f;

    load_stage(sb, 0, 0, Ah, Al, Bh, Bl, rowbase, colbase, tid);
    CP_COMMIT();

    int idq = lane >> 3;
    int bro = ((lane >> 4) << 3) + (lane & 7);
    int bco = ((lane >> 3) & 1) * 16;

    for (int it = 0; it < NITER; it++) {
        if (it + 1 < NITER) {
            load_stage(sb, (it + 1) & 1, (it + 1) * 64, Ah, Al, Bh, Bl,
                       rowbase, colbase, tid);
            CP_COMMIT();
            CP_WAIT(1);
        } else {
            CP_WAIT(0);
        }
        __syncthreads();
        uint32_t st = sb + (it & 1) * STAGE_B;
#pragma unroll
        for (int ks = 0; ks < 4; ks++) {
            uint32_t ah[4][4], al[4][4], bh4[2][4], bl4[2][4];
#pragma unroll
            for (int mt = 0; mt < 4; mt++) {
                int row = wm * 64 + mt * 16 + (idq & 1) * 8 + (lane & 7);
                uint32_t a = st + row * 144 + ks * 32 + (idq >> 1) * 16;
                LDSM_X4(ah[mt], a);
                LDSM_X4(al[mt], a + GMAT);
            }
#pragma unroll
            for (int p = 0; p < 2; p++) {
                int row = wn * 32 + p * 16 + bro;
                uint32_t a = st + 2 * GMAT + row * 144 + ks * 32 + bco;
                LDSM_X4(bh4[p], a);
                LDSM_X4(bl4[p], a + GMAT);
            }
#pragma unroll
            for (int mt = 0; mt < 4; mt++)
#pragma unroll
                for (int nt = 0; nt < 4; nt++) {
                    uint32_t* bhp = bh4[nt >> 1] + (nt & 1) * 2;
                    uint32_t* blp = bl4[nt >> 1] + (nt & 1) * 2;
                    MMA16816(d[mt][nt], ah[mt], bhp);
                    MMA16816(d[mt][nt], ah[mt], blp);
                    MMA16816(d[mt][nt], al[mt], bhp);
                }
        }
        __syncthreads();
    }
}

// ---------------- QKV projection -------------------------------------------
__global__ __launch_bounds__(256, 1)
void gemm_qkv_mma()
{
    extern __shared__ char smem[];
    int z = blockIdx.z;
    int rowbase = blockIdx.y * 128, colbase = blockIdx.x * 128;
    const __nv_bfloat16* Bh = g_Wh + (size_t)z * DD * DD;
    const __nv_bfloat16* Bl = g_Wl + (size_t)z * DD * DD;

    float d[4][4][4];
    gemm_mainloop_mma(g_Xh, g_Xl, Bh, Bl, rowbase, colbase, smem, d);

    int lane = threadIdx.x & 31, warp = threadIdx.x >> 5;
    int wm = warp >> 2, wn = warp & 3;
    // Q gets log2e/sqrt(D) so flash softmax runs in base-2 (ex2.approx direct)
    float scale = (z == 0) ? 0.045086789f : 1.0f;

#pragma unroll
    for (int mt = 0; mt < 4; mt++) {
        int m0 = rowbase + wm * 64 + mt * 16 + (lane >> 2);
#pragma unroll
        for (int nt = 0; nt < 4; nt++) {
            int j = colbase + wn * 32 + nt * 8 + (lane & 3) * 2;   // head-major col
            int hh = j >> 6, cc = j & 63;
#pragma unroll
            for (int rr = 0; rr < 2; rr++) {
                int m = m0 + rr * 8;
                int b = m >> 11, sI = m & (SS - 1);
                float v0 = d[mt][nt][rr * 2] * scale;
                float v1 = d[mt][nt][rr * 2 + 1] * scale;
                if (z == 2) {
                    // V transposed: [bh][c][s] (trunc split, 2B scattered)
                    uint32_t u0 = __float_as_uint(v0), u1 = __float_as_uint(v1);
                    float h0 = __uint_as_float(u0 & 0xFFFF0000u);
                    float h1 = __uint_as_float(u1 & 0xFFFF0000u);
                    size_t o0 = ((size_t)((b * HH + hh) * HDIM + cc)) * SS + sI;
                    size_t o1 = ((size_t)((b * HH + hh) * HDIM + cc + 1)) * SS + sI;
                    *reinterpret_cast<uint16_t*>(&g_Vth[o0]) = (uint16_t)(u0 >> 16);
                    *reinterpret_cast<uint16_t*>(&g_Vtl[o0]) =
                        (uint16_t)(__float_as_uint(v0 - h0) >> 16);
                    *reinterpret_cast<uint16_t*>(&g_Vth[o1]) = (uint16_t)(u1 >> 16);
                    *reinterpret_cast<uint16_t*>(&g_Vtl[o1]) =
                        (uint16_t)(__float_as_uint(v1 - h1) >> 16);
                } else {
                    uint32_t lo, hi = split_pack(v0, v1, lo);
                    size_t o = ((size_t)((b * HH + hh) * SS + sI)) * HDIM + cc;
                    __nv_bfloat16* dh = (z == 0) ? g_Qh : g_Kh;
                    __nv_bfloat16* dl = (z == 0) ? g_Ql : g_Kl;
                    *reinterpret_cast<uint32_t*>(dh + o) = hi;
                    *reinterpret_cast<uint32_t*>(dl + o) = lo;
                }
            }
        }
    }
}

// ---------------- output projection ----------------------------------------
__global__ __launch_bounds__(256, 1)
void gemm_out_mma(float* __restrict__ out)
{
    extern __shared__ char smem[];
    int rowbase = blockIdx.y * 128, colbase = blockIdx.x * 128;
    const __nv_bfloat16* Bh = g_Wh + (size_t)3 * DD * DD;
    const __nv_bfloat16* Bl = g_Wl + (size_t)3 * DD * DD;

    float d[4][4][4];
    gemm_mainloop_mma(g_Ah, g_Al, Bh, Bl, rowbase, colbase, smem, d);

    int lane = threadIdx.x & 31, warp = threadIdx.x >> 5;
    int wm = warp >> 2, wn = warp & 3;
#pragma unroll
    for (int mt = 0; mt < 4; mt++) {
        int m0 = rowbase + wm * 64 + mt * 16 + (lane >> 2);
#pragma unroll
        for (int nt = 0; nt < 4; nt++) {
            int j = colbase + wn * 32 + nt * 8 + (lane & 3) * 2;
#pragma unroll
            for (int rr = 0; rr < 2; rr++) {
                int m = m0 + rr * 8;
                float2 v = make_float2(d[mt][nt][rr * 2], d[mt][nt][rr * 2 + 1]);
                *reinterpret_cast<float2*>(out + (size_t)m * DD + j) = v;
            }
        }
    }
}

// ---------------- flash attention: 256-row Q tile, 8 warps x 32 q-rows ------
// Per-warp body identical to round-15 (proven); CTA aggregates 8 warps so the
// total number of (q-tile, k-block) iterations halves: half the barriers,
// half the K/V cp.async traffic, half the block-boundary pipeline drains.
#define FSTR     144
#define FQROWS   256
#define FQ_BYTES (FQROWS * FSTR)         // 36864 per Q matrix
#define FKV_MAT  (64 * FSTR)             // 9216
#define FST_B    (4 * FKV_MAT)           // 36864 per stage
#define FST_OFF  (2 * FQ_BYTES)          // 73728
#define FSMEM    (FST_OFF + 2 * FST_B)   // 147456

__global__ __launch_bounds__(256)
void flash_mma()
{
    extern __shared__ char smf[];
    uint32_t sb = smem_u32(smf);
    int tid = threadIdx.x, lane = tid & 31, w = tid >> 5;   // 8 warps x 32 rows
    int bh = blockIdx.y, b = bh >> 4, h = bh & 15;
    int qt = (int)gridDim.x - 1 - (int)blockIdx.x;   // heaviest first
    int qbase = qt * FQROWS;

    const __nv_bfloat16* Qhp = g_Qh + (size_t)bh * SS * HDIM;
    const __nv_bfloat16* Qlp = g_Ql + (size_t)bh * SS * HDIM;
    const __nv_bfloat16* Khp = g_Kh + (size_t)bh * SS * HDIM;
    const __nv_bfloat16* Klp = g_Kl + (size_t)bh * SS * HDIM;
    const __nv_bfloat16* Vhp = g_Vth + (size_t)bh * HDIM * SS;
    const __nv_bfloat16* Vlp = g_Vtl + (size_t)bh * HDIM * SS;

    // Q tile (hi+lo): 4096 cp16, 16 per thread
#pragma unroll
    for (int t = 0; t < 16; t++) {
        int f = tid + t * 256;
        int mat = f >> 11, ww = f & 2047;
        int r = ww >> 3, c = ww & 7;
        const __nv_bfloat16* src = (mat ? Qlp : Qhp) + (size_t)(qbase + r) * HDIM + c * 8;
        cp16(sb + mat * FQ_BYTES + r * FSTR + c * 16, src);
    }
    CP_COMMIT();

    auto ldkv = [&](int s, int kb) {
#pragma unroll
        for (int t = 0; t < 8; t++) {
            int f = tid + t * 256;
            int mat = f >> 9, ww = f & 511;
            int r = ww >> 3, c = ww & 7;
            const __nv_bfloat16* src;
            if (mat == 0)      src = Khp + (size_t)(kb * 64 + r) * HDIM + c * 8;
            else if (mat == 1) src = Klp + (size_t)(kb * 64 + r) * HDIM + c * 8;
            else if (mat == 2) src = Vhp + (size_t)r * SS + kb * 64 + c * 8;
            else               src = Vlp + (size_t)r * SS + kb * 64 + c * 8;
            cp16(sb + FST_OFF + s * FST_B + mat * FKV_MAT + r * FSTR + c * 16, src);
        }
    };
    ldkv(0, 0);
    CP_COMMIT();

    float m2[2][2], l2[2][2];
    float o[2][8][4];
#pragma unroll
    for (int mt = 0; mt < 2; mt++) {
        m2[mt][0] = m2[mt][1] = -1e30f;
        l2[mt][0] = l2[mt][1] = 0.f;
#pragma unroll
        for (int nt = 0; nt < 8; nt++)
#pragma unroll
            for (int e = 0; e < 4; e++) o[mt][nt][e] = 0.f;
    }

    // X4 B/V lane mapping: lanes 16-31 address the second n-tile of the pair
    int bro = ((lane >> 4) << 3) + (lane & 7);
    int bco = ((lane >> 3) & 1) * 16;

    int kmax = qbase + w * 32 + 31;      // last valid key for this warp's rows
    int nkb = 4 * qt + 4;
    for (int kb = 0; kb < nkb; kb++) {
        if (kb + 1 < nkb) { ldkv((kb + 1) & 1, kb + 1); CP_COMMIT(); CP_WAIT(1); }
        else              { CP_WAIT(0); }
        __syncthreads();
        uint32_t st = sb + FST_OFF + (kb & 1) * FST_B;
        int kb64 = kb * 64;

        if (kb64 <= kmax) {   // warp-uniform: fully-masked blocks contribute nothing
            // ---- S = Q K^T (hi/lo 3-MMA, 2 m-tiles per warp) ----
            float sc[2][8][4];
#pragma unroll
            for (int mt = 0; mt < 2; mt++)
#pragma unroll
                for (int nt = 0; nt < 8; nt++)
#pragma unroll
                    for (int e = 0; e < 4; e++) sc[mt][nt][e] = 0.f;

#pragma unroll
            for (int kk = 0; kk < 4; kk++) {
                uint32_t ah[2][4], al[2][4];
#pragma unroll
                for (int mt = 0; mt < 2; mt++) {
                    uint32_t qa = sb + (w * 32 + mt * 16 + (lane & 15)) * FSTR +
                                  (lane >> 4) * 16 + kk * 32;
                    LDSM_X4(ah[mt], qa);
                    LDSM_X4(al[mt], qa + FQ_BYTES);
                }
#pragma unroll
                for (int p = 0; p < 4; p++) {
                    uint32_t ka = st + (p * 16 + bro) * FSTR + bco + kk * 32;
                    uint32_t bh4[4], bl4[4];
                    LDSM_X4(bh4, ka);
                    LDSM_X4(bl4, ka + FKV_MAT);
#pragma unroll
                    for (int mt = 0; mt < 2; mt++) {
                        MMA16816(sc[mt][2 * p],     ah[mt], bh4);
                        MMA16816(sc[mt][2 * p],     ah[mt], bl4);
                        MMA16816(sc[mt][2 * p],     al[mt], bh4);
                        MMA16816(sc[mt][2 * p + 1], ah[mt], (bh4 + 2));
                        MMA16816(sc[mt][2 * p + 1], ah[mt], (bl4 + 2));
                        MMA16816(sc[mt][2 * p + 1], al[mt], (bh4 + 2));
                    }
                }
            }

            // ---- causal mask ----
            if (kb64 + 63 > qbase + w * 32) {
#pragma unroll
                for (int mt = 0; mt < 2; mt++) {
                    int qr0 = qbase + w * 32 + mt * 16 + (lane >> 2);
#pragma unroll
                    for (int nt = 0; nt < 8; nt++)
#pragma unroll
                        for (int e = 0; e < 4; e++) {
                            int k = kb64 + nt * 8 + (lane & 3) * 2 + (e & 1);
                            int q = qr0 + (e >> 1) * 8;
                            if (k > q) sc[mt][nt][e] = -1e30f;
                        }
                }
            }

            // ---- online softmax, base-2 (ex2.approx) ----
#pragma unroll
            for (int mt = 0; mt < 2; mt++)
#pragma unroll
                for (int rr = 0; rr < 2; rr++) {
                    float v = -1e30f;
#pragma unroll
                    for (int nt = 0; nt < 8; nt++) {
                        v = fmaxf(v, sc[mt][nt][rr * 2]);
                        v = fmaxf(v, sc[mt][nt][rr * 2 + 1]);
                    }
                    v = fmaxf(v, __shfl_xor_sync(0xffffffffu, v, 1));
                    v = fmaxf(v, __shfl_xor_sync(0xffffffffu, v, 2));
                    float mn = fmaxf(m2[mt][rr], v);
                    float alpha = ex2(m2[mt][rr] - mn);
                    float rs = 0.f;
#pragma unroll
                    for (int nt = 0; nt < 8; nt++) {
                        float p0 = ex2(sc[mt][nt][rr * 2] - mn);
                        float p1 = ex2(sc[mt][nt][rr * 2 + 1] - mn);
                        sc[mt][nt][rr * 2] = p0;
                        sc[mt][nt][rr * 2 + 1] = p1;
                        rs += p0 + p1;
                    }
                    rs += __shfl_xor_sync(0xffffffffu, rs, 1);
                    rs += __shfl_xor_sync(0xffffffffu, rs, 2);
                    l2[mt][rr] = l2[mt][rr] * alpha + rs;
                    m2[mt][rr] = mn;
#pragma unroll
                    for (int nt = 0; nt < 8; nt++) {
                        o[mt][nt][rr * 2] *= alpha;
                        o[mt][nt][rr * 2 + 1] *= alpha;
                    }
                }

            // ---- O += P V (P trunc-split hi/lo via PRMT, 2 m-tiles) ----
#pragma unroll
            for (int kk = 0; kk < 4; kk++) {
                uint32_t aph[2][4], apl[2][4];
#pragma unroll
                for (int mt = 0; mt < 2; mt++)
#pragma unroll
                    for (int half = 0; half < 2; half++) {
                        int tile = 2 * kk + half;
#pragma unroll
                        for (int rr = 0; rr < 2; rr++) {
                            uint32_t lo, hi = split_pack(sc[mt][tile][rr * 2],
                                                         sc[mt][tile][rr * 2 + 1], lo);
                            aph[mt][half * 2 + rr] = hi;
                            apl[mt][half * 2 + rr] = lo;
                        }
                    }
#pragma unroll
                for (int p = 0; p < 4; p++) {
                    uint32_t va = st + 2 * FKV_MAT + (p * 16 + bro) * FSTR + bco + kk * 32;
                    uint32_t vh4[4], vl4[4];
                    LDSM_X4(vh4, va);
                    LDSM_X4(vl4, va + FKV_MAT);
#pragma unroll
                    for (int mt = 0; mt < 2; mt++) {
                        MMA16816(o[mt][2 * p],     aph[mt], vh4);
                        MMA16816(o[mt][2 * p],     aph[mt], vl4);
                        MMA16816(o[mt][2 * p],     apl[mt], vh4);
                        MMA16816(o[mt][2 * p + 1], aph[mt], (vh4 + 2));
                        MMA16816(o[mt][2 * p + 1], aph[mt], (vl4 + 2));
                        MMA16816(o[mt][2 * p + 1], apl[mt], (vh4 + 2));
                    }
                }
            }
        }
        __syncthreads();
    }

    // ---- epilogue: normalize, write [b][s][h*64+c] bf16 hi/lo ----
#pragma unroll
    for (int mt = 0; mt < 2; mt++)
#pragma unroll
        for (int rr = 0; rr < 2; rr++) {
            float inv = 1.f / l2[mt][rr];
            int q = qbase + w * 32 + mt * 16 + (lane >> 2) + rr * 8;
            size_t rowo = ((size_t)b * SS + q) * DD + h * 64;
#pragma unroll
            for (int nt = 0; nt < 8; nt++) {
                int c = nt * 8 + (lane & 3) * 2;
                uint32_t lo, hi = split_pack(o[mt][nt][rr * 2] * inv,
                                             o[mt][nt][rr * 2 + 1] * inv, lo);
                *reinterpret_cast<uint32_t*>(g_Ah + rowo + c) = hi;
                *reinterpret_cast<uint32_t*>(g_Al + rowo + c) = lo;
            }
        }
}

// ---------------------------------------------------------------------------
extern "C" void kernel_launch(void* const* d_in, const int* in_sizes, int n_in,
                              void* d_out, int out_size)
{
    const float* x  = (const float*)d_in[0];
    const float* qw = (const float*)d_in[1];
    const float* kw = (const float*)d_in[2];
    const float* vw = (const float*)d_in[3];
    const float* ow = (const float*)d_in[4];
    float* out = (float*)d_out;

    cudaFuncSetAttribute(gemm_qkv_mma,
                         cudaFuncAttributeMaxDynamicSharedMemorySize, GSMEM);
    cudaFuncSetAttribute(gemm_out_mma,
                         cudaFuncAttributeMaxDynamicSharedMemorySize, GSMEM);
    cudaFuncSetAttribute(flash_mma,
                         cudaFuncAttributeMaxDynamicSharedMemorySize, FSMEM);

    split_x<<<MM * DD / 256, 256>>>(x);
    prep_w<<<dim3(DD / 32, DD / 32, 4), dim3(32, 32)>>>(qw, kw, vw, ow);
    gemm_qkv_mma<<<dim3(DD / 128, MM / 128, 3), 256, GSMEM>>>();
    flash_mma<<<dim3(SS / FQROWS, BB * HH), 256, FSMEM>>>();
    gemm_out_mma<<<dim3(DD / 128, MM / 128), 256, GSMEM>>>(out);
}

// round 17
// speedup vs baseline: 1.0454x; 1.0454x over previous
#include <cuda_runtime.h>
#include <cuda_bf16.h>
#include <cstdint>

#define BB   2
#define SS   2048
#define DD   1024
#define HH   16
#define HDIM 64
#define MM   (BB*SS)

// ---------------- scratch (__device__ globals; allocation-free rule) -------
__device__ __nv_bfloat16 g_Qh[BB*HH*SS*HDIM], g_Ql[BB*HH*SS*HDIM];  // [bh][s][c], scaled log2e/32
__device__ __nv_bfloat16 g_Kh[BB*HH*SS*HDIM], g_Kl[BB*HH*SS*HDIM];  // [bh][s][c]
__device__ __nv_bfloat16 g_Vth[BB*HH*SS*HDIM], g_Vtl[BB*HH*SS*HDIM];// [bh][c][s] transposed
__device__ __nv_bfloat16 g_Xh[MM*DD],  g_Xl[MM*DD];                 // x split hi/lo
__device__ __nv_bfloat16 g_Wh[4*DD*DD], g_Wl[4*DD*DD];              // W^T (permuted) hi/lo
__device__ __nv_bfloat16 g_Ah[MM*DD],  g_Al[MM*DD];                 // attn out [b][s][h*64+c]

// ---------------- helpers ---------------------------------------------------
__device__ __forceinline__ uint32_t smem_u32(const void* p) {
    uint32_t a;
    asm("{ .reg .u64 t; cvta.to.shared.u64 t, %1; cvt.u32.u64 %0, t; }" : "=r"(a) : "l"(p));
    return a;
}
__device__ __forceinline__ void cp16(uint32_t dst, const void* src) {
    asm volatile("cp.async.ca.shared.global [%0], [%1], 16;" :: "r"(dst), "l"(src));
}
#define CP_COMMIT() asm volatile("cp.async.commit_group;" ::: "memory")
#define CP_WAIT(n)  asm volatile("cp.async.wait_group %0;" :: "n"(n) : "memory")

#define LDSM_X4(r, a)                                                        \
    asm volatile("ldmatrix.sync.aligned.m8n8.x4.shared.b16 {%0,%1,%2,%3}, [%4];" \
        : "=r"((r)[0]), "=r"((r)[1]), "=r"((r)[2]), "=r"((r)[3]) : "r"(a))

#define MMA16816(d, a, b)                                                    \
    asm volatile("mma.sync.aligned.m16n8k16.row.col.f32.bf16.bf16.f32 "      \
        "{%0,%1,%2,%3}, {%4,%5,%6,%7}, {%8,%9}, {%0,%1,%2,%3};"              \
        : "+f"((d)[0]), "+f"((d)[1]), "+f"((d)[2]), "+f"((d)[3])             \
        : "r"((a)[0]), "r"((a)[1]), "r"((a)[2]), "r"((a)[3]),                \
          "r"((b)[0]), "r"((b)[1]))

__device__ __forceinline__ uint32_t prmt(uint32_t a, uint32_t b, uint32_t sel) {
    uint32_t r;
    asm("prmt.b32 %0, %1, %2, %3;" : "=r"(r) : "r"(a), "r"(b), "r"(sel));
    return r;
}
__device__ __forceinline__ float ex2(float x) {
    float r;
    asm("ex2.approx.f32 %0, %1;" : "=f"(r) : "f"(x));
    return r;
}

// truncation-based hi/lo bf16 split of (v0,v1): hi packed return, lo out-param.
__device__ __forceinline__ uint32_t split_pack(float v0, float v1, uint32_t& lo) {
    uint32_t u0 = __float_as_uint(v0), u1 = __float_as_uint(v1);
    uint32_t hi = prmt(u0, u1, 0x7632);
    float h0 = __uint_as_float(u0 & 0xFFFF0000u);
    float h1 = __uint_as_float(u1 & 0xFFFF0000u);
    lo = prmt(__float_as_uint(v0 - h0), __float_as_uint(v1 - h1), 0x7632);
    return hi;
}

// ---------------- prep kernels ---------------------------------------------
__global__ __launch_bounds__(256)
void split_x(const float* __restrict__ x)
{
    int i = blockIdx.x * 256 + threadIdx.x;
    float v = x[i];
    __nv_bfloat16 h = __float2bfloat16(v);
    g_Xh[i] = h;
    g_Xl[i] = __float2bfloat16(v - __bfloat162float(h));
}

// z<3 (qw,kw,vw): W^T with head-permuted columns; z==3 (ow): W^T with permuted k.
__global__ void prep_w(const float* __restrict__ qw, const float* __restrict__ kw,
                       const float* __restrict__ vw, const float* __restrict__ ow)
{
    __shared__ float tile[32][33];
    int z = blockIdx.z;
    const float* W = (z == 0) ? qw : (z == 1) ? kw : (z == 2) ? vw : ow;
    int kbase = blockIdx.y * 32, jbase = blockIdx.x * 32;
    int tx = threadIdx.x, ty = threadIdx.y;
    tile[ty][tx] = W[(kbase + ty) * DD + jbase + tx];
    __syncthreads();
    int j = jbase + ty;
    int k = kbase + tx;
    float v = tile[tx][ty];                 // = W[k][j]
    __nv_bfloat16 h = __float2bfloat16(v);
    size_t o;
    if (z < 3) {
        int jp = (j & 15) * 64 + (j >> 4);
        o = (size_t)z * DD * DD + (size_t)jp * DD + k;
    } else {
        int kp = (k & 15) * 64 + (k >> 4);
        o = (size_t)3 * DD * DD + (size_t)j * DD + kp;
    }
    g_Wh[o] = h;
    g_Wl[o] = __float2bfloat16(v - __bfloat162float(h));
}

// ---------------- mma.sync GEMM mainloop (round-14 proven, unchanged) -------
#define GMAT    18432
#define STAGE_B (4 * GMAT)
#define GSMEM   (2 * STAGE_B)               // 147456
#define NITER   (DD / 64)                   // 16

__device__ __forceinline__ void load_stage(
    uint32_t sb, int s, int kt,
    const __nv_bfloat16* __restrict__ Ah, const __nv_bfloat16* __restrict__ Al,
    const __nv_bfloat16* __restrict__ Bh, const __nv_bfloat16* __restrict__ Bl,
    int rowbase, int colbase, int tid)
{
    uint32_t base = sb + s * STAGE_B;
#pragma unroll
    for (int t = 0; t < 16; t++) {
        int f = tid + t * 256;
        int mat = f >> 10;                  // 0:Ah 1:Al 2:Bh 3:Bl
        int w = f & 1023;
        int r = w >> 3, c = w & 7;          // row 0-127, 16B chunk 0-7
        int rb = (mat < 2) ? rowbase : colbase;
        const __nv_bfloat16* src = ((mat == 0) ? Ah : (mat == 1) ? Al :
                                    (mat == 2) ? Bh : Bl) +
                                   (size_t)(rb + r) * DD + kt + c * 8;
        cp16(base + mat * GMAT + r * 144 + c * 16, src);
    }
}

__device__ __forceinline__ void gemm_mainloop_mma(
    const __nv_bfloat16* __restrict__ Ah, const __nv_bfloat16* __restrict__ Al,
    const __nv_bfloat16* __restrict__ Bh, const __nv_bfloat16* __restrict__ Bl,
    int rowbase, int colbase, char* smem, float d[4][4][4])
{
    uint32_t sb = smem_u32(smem);
    int tid = threadIdx.x;
    int lane = tid & 31, warp = tid >> 5;
    int wm = warp >> 2, wn = warp & 3;

#pragma unroll
    for (int mt = 0; mt < 4; mt++)
#pragma unroll
        for (int nt = 0; nt < 4; nt++)
#pragma unroll
            for (int e = 0; e < 4; e++) d[mt][nt][e] = 0.f;

    load_stage(sb, 0, 0, Ah, Al, Bh, Bl, rowbase, colbase, tid);
    CP_COMMIT();

    int idq = lane >> 3;
    int bro = ((lane >> 4) << 3) + (lane & 7);
    int bco = ((lane >> 3) & 1) * 16;

    for (int it = 0; it < NITER; it++) {
        if (it + 1 < NITER) {
            load_stage(sb, (it + 1) & 1, (it + 1) * 64, Ah, Al, Bh, Bl,
                       rowbase, colbase, tid);
            CP_COMMIT();
            CP_WAIT(1);
        } else {
            CP_WAIT(0);
        }
        __syncthreads();
        uint32_t st = sb + (it & 1) * STAGE_B;
#pragma unroll
        for (int ks = 0; ks < 4; ks++) {
            uint32_t ah[4][4], al[4][4], bh4[2][4], bl4[2][4];
#pragma unroll
            for (int mt = 0; mt < 4; mt++) {
                int row = wm * 64 + mt * 16 + (idq & 1) * 8 + (lane & 7);
                uint32_t a = st + row * 144 + ks * 32 + (idq >> 1) * 16;
                LDSM_X4(ah[mt], a);
                LDSM_X4(al[mt], a + GMAT);
            }
#pragma unroll
            for (int p = 0; p < 2; p++) {
                int row = wn * 32 + p * 16 + bro;
                uint32_t a = st + 2 * GMAT + row * 144 + ks * 32 + bco;
                LDSM_X4(bh4[p], a);
                LDSM_X4(bl4[p], a + GMAT);
            }
#pragma unroll
            for (int mt = 0; mt < 4; mt++)
#pragma unroll
                for (int nt = 0; nt < 4; nt++) {
                    uint32_t* bhp = bh4[nt >> 1] + (nt & 1) * 2;
                    uint32_t* blp = bl4[nt >> 1] + (nt & 1) * 2;
                    MMA16816(d[mt][nt], ah[mt], bhp);
                    MMA16816(d[mt][nt], ah[mt], blp);
                    MMA16816(d[mt][nt], al[mt], bhp);
                }
        }
        __syncthreads();
    }
}

// ---------------- QKV projection -------------------------------------------
__global__ __launch_bounds__(256, 1)
void gemm_qkv_mma()
{
    extern __shared__ char smem[];
    int z = blockIdx.z;
    int rowbase = blockIdx.y * 128, colbase = blockIdx.x * 128;
    const __nv_bfloat16* Bh = g_Wh + (size_t)z * DD * DD;
    const __nv_bfloat16* Bl = g_Wl + (size_t)z * DD * DD;

    float d[4][4][4];
    gemm_mainloop_mma(g_Xh, g_Xl, Bh, Bl, rowbase, colbase, smem, d);

    int lane = threadIdx.x & 31, warp = threadIdx.x >> 5;
    int wm = warp >> 2, wn = warp & 3;
    // Q gets log2e/sqrt(D) so flash softmax runs in base-2 (ex2.approx direct)
    float scale = (z == 0) ? 0.045086789f : 1.0f;

#pragma unroll
    for (int mt = 0; mt < 4; mt++) {
        int m0 = rowbase + wm * 64 + mt * 16 + (lane >> 2);
#pragma unroll
        for (int nt = 0; nt < 4; nt++) {
            int j = colbase + wn * 32 + nt * 8 + (lane & 3) * 2;   // head-major col
            int hh = j >> 6, cc = j & 63;
#pragma unroll
            for (int rr = 0; rr < 2; rr++) {
                int m = m0 + rr * 8;
                int b = m >> 11, sI = m & (SS - 1);
                float v0 = d[mt][nt][rr * 2] * scale;
                float v1 = d[mt][nt][rr * 2 + 1] * scale;
                if (z == 2) {
                    // V transposed: [bh][c][s] (trunc split, 2B scattered)
                    uint32_t u0 = __float_as_uint(v0), u1 = __float_as_uint(v1);
                    float h0 = __uint_as_float(u0 & 0xFFFF0000u);
                    float h1 = __uint_as_float(u1 & 0xFFFF0000u);
                    size_t o0 = ((size_t)((b * HH + hh) * HDIM + cc)) * SS + sI;
                    size_t o1 = ((size_t)((b * HH + hh) * HDIM + cc + 1)) * SS + sI;
                    *reinterpret_cast<uint16_t*>(&g_Vth[o0]) = (uint16_t)(u0 >> 16);
                    *reinterpret_cast<uint16_t*>(&g_Vtl[o0]) =
                        (uint16_t)(__float_as_uint(v0 - h0) >> 16);
                    *reinterpret_cast<uint16_t*>(&g_Vth[o1]) = (uint16_t)(u1 >> 16);
                    *reinterpret_cast<uint16_t*>(&g_Vtl[o1]) =
                        (uint16_t)(__float_as_uint(v1 - h1) >> 16);
                } else {
                    uint32_t lo, hi = split_pack(v0, v1, lo);
                    size_t o = ((size_t)((b * HH + hh) * SS + sI)) * HDIM + cc;
                    __nv_bfloat16* dh = (z == 0) ? g_Qh : g_Kh;
                    __nv_bfloat16* dl = (z == 0) ? g_Ql : g_Kl;
                    *reinterpret_cast<uint32_t*>(dh + o) = hi;
                    *reinterpret_cast<uint32_t*>(dl + o) = lo;
                }
            }
        }
    }
}

// ---------------- output projection ----------------------------------------
__global__ __launch_bounds__(256, 1)
void gemm_out_mma(float* __restrict__ out)
{
    extern __shared__ char smem[];
    int rowbase = blockIdx.y * 128, colbase = blockIdx.x * 128;
    const __nv_bfloat16* Bh = g_Wh + (size_t)3 * DD * DD;
    const __nv_bfloat16* Bl = g_Wl + (size_t)3 * DD * DD;

    float d[4][4][4];
    gemm_mainloop_mma(g_Ah, g_Al, Bh, Bl, rowbase, colbase, smem, d);

    int lane = threadIdx.x & 31, warp = threadIdx.x >> 5;
    int wm = warp >> 2, wn = warp & 3;
#pragma unroll
    for (int mt = 0; mt < 4; mt++) {
        int m0 = rowbase + wm * 64 + mt * 16 + (lane >> 2);
#pragma unroll
        for (int nt = 0; nt < 4; nt++) {
            int j = colbase + wn * 32 + nt * 8 + (lane & 3) * 2;
#pragma unroll
            for (int rr = 0; rr < 2; rr++) {
                int m = m0 + rr * 8;
                float2 v = make_float2(d[mt][nt][rr * 2], d[mt][nt][rr * 2 + 1]);
                *reinterpret_cast<float2*>(out + (size_t)m * DD + j) = v;
            }
        }
    }
}

// ---------------- flash attention: cross-block pipelined --------------------
// 8 warps x 16 q-rows (proven layout), 3-stage K/V ring. softmax(kb) and
// QK(kb+1) share one basic block with no dependency -> ptxas interleaves the
// scalar softmax chain with the next block's MMA stream.
#define FSTR     144
#define FQ_BYTES (128 * FSTR)            // 18432 per Q matrix
#define FKV_MAT  (64 * FSTR)             // 9216
#define FST_B    (4 * FKV_MAT)           // 36864 per stage
#define FST_OFF  (2 * FQ_BYTES)          // 36864
#define FSMEM    (FST_OFF + 3 * FST_B)   // 147456

__global__ __launch_bounds__(256)
void flash_mma()
{
    extern __shared__ char smf[];
    uint32_t sb = smem_u32(smf);
    int tid = threadIdx.x, lane = tid & 31, w = tid >> 5;
    int bh = blockIdx.y, b = bh >> 4, h = bh & 15;
    int qt = (int)gridDim.x - 1 - (int)blockIdx.x;   // heaviest first
    int qbase = qt * 128;

    const __nv_bfloat16* Qhp = g_Qh + (size_t)bh * SS * HDIM;
    const __nv_bfloat16* Qlp = g_Ql + (size_t)bh * SS * HDIM;
    const __nv_bfloat16* Khp = g_Kh + (size_t)bh * SS * HDIM;
    const __nv_bfloat16* Klp = g_Kl + (size_t)bh * SS * HDIM;
    const __nv_bfloat16* Vhp = g_Vth + (size_t)bh * HDIM * SS;
    const __nv_bfloat16* Vlp = g_Vtl + (size_t)bh * HDIM * SS;

    auto ldkv = [&](int s, int kb) {
#pragma unroll
        for (int t = 0; t < 8; t++) {
            int f = tid + t * 256;
            int mat = f >> 9, ww = f & 511;
            int r = ww >> 3, c = ww & 7;
            const __nv_bfloat16* src;
            if (mat == 0)      src = Khp + (size_t)(kb * 64 + r) * HDIM + c * 8;
            else if (mat == 1) src = Klp + (size_t)(kb * 64 + r) * HDIM + c * 8;
            else if (mat == 2) src = Vhp + (size_t)r * SS + kb * 64 + c * 8;
            else               src = Vlp + (size_t)r * SS + kb * 64 + c * 8;
            cp16(sb + FST_OFF + s * FST_B + mat * FKV_MAT + r * FSTR + c * 16, src);
        }
    };

    // group0: Q tile + K/V stage 0
#pragma unroll
    for (int t = 0; t < 8; t++) {
        int f = tid + t * 256;
        int mat = f >> 10, ww = f & 1023;
        int r = ww >> 3, c = ww & 7;
        const __nv_bfloat16* src = (mat ? Qlp : Qhp) + (size_t)(qbase + r) * HDIM + c * 8;
        cp16(sb + mat * FQ_BYTES + r * FSTR + c * 16, src);
    }
    ldkv(0, 0);
    CP_COMMIT();
    ldkv(1, 1);          // group1 (nkb >= 2 always)
    CP_COMMIT();
    CP_WAIT(1);          // group0 (Q + stage 0) done
    __syncthreads();

    float m2[2] = {-1e30f, -1e30f}, l2[2] = {0.f, 0.f};
    float o[8][4], scA[8][4], scB[8][4];
#pragma unroll
    for (int nt = 0; nt < 8; nt++)
#pragma unroll
        for (int e = 0; e < 4; e++) o[nt][e] = 0.f;

    int bro = ((lane >> 4) << 3) + (lane & 7);
    int bco = ((lane >> 3) & 1) * 16;
    int kmax = qbase + w * 16 + 15;
    int nkb = 2 * qt + 2;

    auto qk = [&](float (&sc)[8][4], uint32_t st) {
#pragma unroll
        for (int nt = 0; nt < 8; nt++)
#pragma unroll
            for (int e = 0; e < 4; e++) sc[nt][e] = 0.f;
#pragma unroll
        for (int kk = 0; kk < 4; kk++) {
            uint32_t ah[4], al[4];
            uint32_t qa = sb + (w * 16 + (lane & 15)) * FSTR + (lane >> 4) * 16 + kk * 32;
            LDSM_X4(ah, qa);
            LDSM_X4(al, qa + FQ_BYTES);
#pragma unroll
            for (int p = 0; p < 4; p++) {
                uint32_t ka = st + (p * 16 + bro) * FSTR + bco + kk * 32;
                uint32_t bh4[4], bl4[4];
                LDSM_X4(bh4, ka);
                LDSM_X4(bl4, ka + FKV_MAT);
                MMA16816(sc[2 * p],     ah, bh4);
                MMA16816(sc[2 * p],     ah, bl4);
                MMA16816(sc[2 * p],     al, bh4);
                MMA16816(sc[2 * p + 1], ah, (bh4 + 2));
                MMA16816(sc[2 * p + 1], ah, (bl4 + 2));
                MMA16816(sc[2 * p + 1], al, (bh4 + 2));
            }
        }
    };

    auto masksm = [&](int kb, float (&sc)[8][4]) {
        int kb64 = kb * 64;
        int qr0 = qbase + w * 16 + (lane >> 2);
        if (kb64 + 63 > qbase + w * 16) {
#pragma unroll
            for (int nt = 0; nt < 8; nt++)
#pragma unroll
                for (int e = 0; e < 4; e++) {
                    int k = kb64 + nt * 8 + (lane & 3) * 2 + (e & 1);
                    int q = qr0 + (e >> 1) * 8;
                    if (k > q) sc[nt][e] = -1e30f;
                }
        }
#pragma unroll
        for (int rr = 0; rr < 2; rr++) {
            float v = -1e30f;
#pragma unroll
            for (int nt = 0; nt < 8; nt++) {
                v = fmaxf(v, sc[nt][rr * 2]);
                v = fmaxf(v, sc[nt][rr * 2 + 1]);
            }
            v = fmaxf(v, __shfl_xor_sync(0xffffffffu, v, 1));
            v = fmaxf(v, __shfl_xor_sync(0xffffffffu, v, 2));
            float mn = fmaxf(m2[rr], v);
            float alpha = ex2(m2[rr] - mn);
            float rs = 0.f;
#pragma unroll
            for (int nt = 0; nt < 8; nt++) {
                float p0 = ex2(sc[nt][rr * 2] - mn);
                float p1 = ex2(sc[nt][rr * 2 + 1] - mn);
                sc[nt][rr * 2] = p0;
                sc[nt][rr * 2 + 1] = p1;
                rs += p0 + p1;
            }
            rs += __shfl_xor_sync(0xffffffffu, rs, 1);
            rs += __shfl_xor_sync(0xffffffffu, rs, 2);
            l2[rr] = l2[rr] * alpha + rs;
            m2[rr] = mn;
#pragma unroll
            for (int nt = 0; nt < 8; nt++) {
                o[nt][rr * 2] *= alpha;
                o[nt][rr * 2 + 1] *= alpha;
            }
        }
    };

    auto pv = [&](float (&sc)[8][4], uint32_t st) {
#pragma unroll
        for (int kk = 0; kk < 4; kk++) {
            uint32_t aph[4], apl[4];
#pragma unroll
            for (int half = 0; half < 2; half++) {
                int tile = 2 * kk + half;
#pragma unroll
                for (int rr = 0; rr < 2; rr++) {
                    uint32_t lo, hi = split_pack(sc[tile][rr * 2],
                                                 sc[tile][rr * 2 + 1], lo);
                    aph[half * 2 + rr] = hi;
                    apl[half * 2 + rr] = lo;
                }
            }
#pragma unroll
            for (int p = 0; p < 4; p++) {
                uint32_t va = st + 2 * FKV_MAT + (p * 16 + bro) * FSTR + bco + kk * 32;
                uint32_t vh4[4], vl4[4];
                LDSM_X4(vh4, va);
                LDSM_X4(vl4, va + FKV_MAT);
                MMA16816(o[2 * p],     aph, vh4);
                MMA16816(o[2 * p],     aph, vl4);
                MMA16816(o[2 * p],     apl, vh4);
                MMA16816(o[2 * p + 1], aph, (vh4 + 2));
                MMA16816(o[2 * p + 1], aph, (vl4 + 2));
                MMA16816(o[2 * p + 1], apl, (vh4 + 2));
            }
        }
    };

    qk(scA, sb + FST_OFF);               // block 0 scores (stage 0)

    // step: needs stage kb (PV) and kb+1 (QK) ready; prefetches kb+2.
    auto step = [&](int kb, float (&cur)[8][4], float (&nxt)[8][4]) {
        CP_WAIT(0);                       // stage kb+1 complete
        __syncthreads();                  // visible to all; stage (kb+2)%3 free
        if (kb + 2 < nkb) { ldkv((kb + 2) % 3, kb + 2); CP_COMMIT(); }
        uint32_t stc = sb + FST_OFF + (kb % 3) * FST_B;
        uint32_t stn = sb + FST_OFF + ((kb + 1) % 3) * FST_B;
        bool doNext = (kb + 1 < nkb) && ((kb + 1) * 64 <= kmax);
        bool doCur  = (kb * 64 <= kmax);
        if (doNext) {                     // one BB: softmax || next-block QK
            masksm(kb, cur);
            qk(nxt, stn);
            pv(cur, stc);
        } else if (doCur) {
            masksm(kb, cur);
            pv(cur, stc);
        }
    };

    for (int kb = 0; kb < nkb; kb += 2) { // nkb always even
        step(kb, scA, scB);
        step(kb + 1, scB, scA);
    }

    // ---- epilogue: normalize, write [b][s][h*64+c] bf16 hi/lo ----
#pragma unroll
    for (int rr = 0; rr < 2; rr++) {
        float inv = 1.f / l2[rr];
        int q = qbase + w * 16 + (lane >> 2) + rr * 8;
        size_t rowo = ((size_t)b * SS + q) * DD + h * 64;
#pragma unroll
        for (int nt = 0; nt < 8; nt++) {
            int c = nt * 8 + (lane & 3) * 2;
            uint32_t lo, hi = split_pack(o[nt][rr * 2] * inv, o[nt][rr * 2 + 1] * inv, lo);
            *reinterpret_cast<uint32_t*>(g_Ah + rowo + c) = hi;
            *reinterpret_cast<uint32_t*>(g_Al + rowo + c) = lo;
        }
    }
}

// ---------------------------------------------------------------------------
extern "C" void kernel_launch(void* const* d_in, const int* in_sizes, int n_in,
                              void* d_out, int out_size)
{
    const float* x  = (const float*)d_in[0];
    const float* qw = (const float*)d_in[1];
    const float* kw = (const float*)d_in[2];
    const float* vw = (const float*)d_in[3];
    const float* ow = (const float*)d_in[4];
    float* out = (float*)d_out;

    cudaFuncSetAttribute(gemm_qkv_mma,
                         cudaFuncAttributeMaxDynamicSharedMemorySize, GSMEM);
    cudaFuncSetAttribute(gemm_out_mma,
                         cudaFuncAttributeMaxDynamicSharedMemorySize, GSMEM);
    cudaFuncSetAttribute(flash_mma,
                         cudaFuncAttributeMaxDynamicSharedMemorySize, FSMEM);

    split_x<<<MM * DD / 256, 256>>>(x);
    prep_w<<<dim3(DD / 32, DD / 32, 4), dim3(32, 32)>>>(qw, kw, vw, ow);
    gemm_qkv_mma<<<dim3(DD / 128, MM / 128, 3), 256, GSMEM>>>();
    flash_mma<<<dim3(SS / 128, BB * HH), 256, FSMEM>>>();
    gemm_out_mma<<<dim3(DD / 128, MM / 128), 256, GSMEM>>>(out);
}